// round 15
// baseline (speedup 1.0000x reference)
#include <cuda_runtime.h>
#include <cuda_bf16.h>

typedef unsigned int u32;
typedef unsigned short u16;
typedef unsigned long long u64;

#define GRID   128
#define NTHR   512
#define TLEN   168
#define SEQ    169
#define NSTEPS 24
#define PB     80                 // H row pitch in bytes

#define H1B    10240              // one H1 buffer: 128 rows (0-63 hi, 64-127 lo)
#define H2B    20480              // one H2 buffer: 256 rows (0-127 hi, 128-255 lo)
#define OFF_H1   0
#define OFF_H2   (2*H1B)                    // 20480
#define OFF_ALO1 (OFF_H2 + 2*H2B)           // 61440  (4 kk x 512 x 16B)
#define OFF_ALO2 (OFF_ALO1 + 32768)         // 94208  (8 kk x 512 x 16B)
#define OFF_WIN  (OFF_ALO2 + 65536)         // 159744
#define OFF_SCR  (OFF_WIN + 192*32*4)       // 184320
#define OFF_MISC (OFF_SCR + 64*32*4)        // 192512
#define SMEM_BYTES (OFF_MISC + 512)         // 193024

// r1 ring (one step deep), separate bf16 hi/lo planes: [GRID][TLEN][64 units][32 batches]
__device__ u16 g_r1h[(size_t)GRID * TLEN * 64 * 32];
__device__ u16 g_r1l[(size_t)GRID * TLEN * 64 * 32];

static __device__ __forceinline__ float rcpf(float x){float r;asm("rcp.approx.f32 %0,%1;":"=f"(r):"f"(x));return r;}
static __device__ __forceinline__ float sigf(float x){return rcpf(1.0f+__expf(-x));}
static __device__ __forceinline__ float tanhf_(float x){return fmaf(2.0f,sigf(2.0f*x),-1.0f);}

// hi = truncated top-16 pair (PRMT), lo = rn(bf16) of remainders, packed
static __device__ __forceinline__ void splitpack2(float x0,float x1,u32&hi,u32&lo){
    u32 a=__float_as_uint(x0), b=__float_as_uint(x1);
    asm("prmt.b32 %0,%1,%2,0x7632;":"=r"(hi):"r"(a),"r"(b));
    float r0=x0-__uint_as_float(a&0xffff0000u);
    float r1=x1-__uint_as_float(b&0xffff0000u);
    asm("cvt.rn.bf16x2.f32 %0,%1,%2;":"=r"(lo):"f"(r1),"f"(r0));
}
static __device__ __forceinline__ void mma4(float c[4],const u32 a[4],u32 b0,u32 b1){
    asm volatile("mma.sync.aligned.m16n8k16.row.col.f32.bf16.bf16.f32 "
        "{%0,%1,%2,%3},{%4,%5,%6,%7},{%8,%9},{%0,%1,%2,%3};"
        :"+f"(c[0]),"+f"(c[1]),"+f"(c[2]),"+f"(c[3])
        :"r"(a[0]),"r"(a[1]),"r"(a[2]),"r"(a[3]),"r"(b0),"r"(b1));
}
static __device__ __forceinline__ void ldm4t(u32 addr,u32&r0,u32&r1,u32&r2,u32&r3){
    asm volatile("ldmatrix.sync.aligned.m8n8.x4.trans.shared.b16 {%0,%1,%2,%3}, [%4];"
        :"=r"(r0),"=r"(r1),"=r"(r2),"=r"(r3):"r"(addr));
}
static __device__ __forceinline__ void lds128(u32 addr,u32 r[4]){
    asm volatile("ld.shared.v4.u32 {%0,%1,%2,%3}, [%4];"
        :"=r"(r[0]),"=r"(r[1]),"=r"(r[2]),"=r"(r[3]):"r"(addr));
}

// split-precision GEMM, 2 independent accumulator groups.
// LOROWS: row offset of the lo-plane within the H buffer.
template<int KK, int LOROWS>
static __device__ __forceinline__ void do_mma(u32 hb, u32 alo0,
                                              const u32 Ahi[][4],
                                              float cP[4][4], float cQ[4][4])
{
    #pragma unroll
    for (int kk = 0; kk < KK; kk++) {
        u32 a0 = hb + (u32)(kk * 16 * PB);
        u32 al[4];
        lds128(alo0 + (u32)(kk * 8192), al);
        u32 b0,b1,b2,b3,b4,b5,b6,b7;
        u32 l0,l1,l2,l3,l4,l5,l6,l7;
        ldm4t(a0,                 b0,b1,b2,b3);
        ldm4t(a0+32,              b4,b5,b6,b7);
        ldm4t(a0+LOROWS*PB,       l0,l1,l2,l3);
        ldm4t(a0+LOROWS*PB+32,    l4,l5,l6,l7);
        mma4(cP[0], Ahi[kk], b0, b1);
        mma4(cP[1], Ahi[kk], b2, b3);
        mma4(cP[2], Ahi[kk], b4, b5);
        mma4(cP[3], Ahi[kk], b6, b7);
        mma4(cQ[0], Ahi[kk], l0, l1);
        mma4(cQ[1], Ahi[kk], l2, l3);
        mma4(cQ[2], Ahi[kk], l4, l5);
        mma4(cQ[3], Ahi[kk], l6, l7);
        mma4(cP[0], al, b0, b1);
        mma4(cP[1], al, b2, b3);
        mma4(cP[2], al, b4, b5);
        mma4(cP[3], al, b6, b7);
    }
}

__global__ void __launch_bounds__(NTHR, 1)
lstm_rec_kernel(const float* __restrict__ x,
                const float* __restrict__ Wih1, const float* __restrict__ Whh1,
                const float* __restrict__ bih1, const float* __restrict__ bhh1,
                const float* __restrict__ Wih2, const float* __restrict__ Whh2,
                const float* __restrict__ bih2, const float* __restrict__ bhh2,
                const float* __restrict__ fc1w, const float* __restrict__ fc1b,
                const float* __restrict__ fc2w, const float* __restrict__ fc2b,
                float* __restrict__ out)
{
    extern __shared__ char sm[];
    float* win   = (float*)(sm + OFF_WIN);   // [192][32] t-major
    float* scr   = (float*)(sm + OFF_SCR);   // [64][32]
    float* wcomb = (float*)(sm + OFF_MISC);  // [65]
    float* bcs   = wcomb + 65;
    float* dsh   = wcomb + 66;               // [32]
    u32*   alo1s = (u32*)(sm + OFF_ALO1);
    u32*   alo2s = (u32*)(sm + OFF_ALO2);

    const int tid  = threadIdx.x;
    const int b0g  = blockIdx.x * 32;
    const int warp = tid >> 5, lane = tid & 31;
    const int g    = lane >> 2, tg = lane & 3;
    const int q    = 4*warp + (g & 3);                 // this thread's unit
    const bool glo = (g < 4);
    const int bb0  = (glo ? 0 : 16) + 2*tg;            // batches bb0,bb0+1,bb0+8,bb0+9
    const int rowA = (g >> 2)*64 + 4*warp + (g & 3);   // W row for C-tile row g

    const u32 hsm1 = (u32)__cvta_generic_to_shared(sm + OFF_H1);
    const u32 hsm2 = (u32)__cvta_generic_to_shared(sm + OFF_H2);
    const u32 alo1 = (u32)__cvta_generic_to_shared(alo1s) + (u32)tid * 16;
    const u32 alo2 = (u32)__cvta_generic_to_shared(alo2s) + (u32)tid * 16;
    const u32 laneoff = (u32)((lane & 7) * PB + ((lane >> 3) & 1) * (8 * PB) + (lane >> 4) * 16);

    // ---- one-time init ----
    for (int i = tid; i < TLEN*32; i += NTHR) {
        int t = i >> 5, b = i & 31;
        win[t*32 + b] = x[(size_t)(b0g + b)*SEQ + t];
    }
    if (tid < 32) dsh[tid] = x[(size_t)(b0g + tid)*SEQ + TLEN];
    if (tid < 65) {
        float s = 0.0f;
        for (int j = 0; j < 64; j++) s = fmaf(fc2w[j], fc1w[j*65 + tid], s);
        wcomb[tid] = s;
    }
    if (tid == 65) {
        float s = fc2b[0];
        for (int j = 0; j < 64; j++) s = fmaf(fc2w[j], fc1b[j], s);
        *bcs = s;
    }
    float wi1f[4], b1f[4], b2f[4];
    #pragma unroll
    for (int ga = 0; ga < 4; ga++) {
        wi1f[ga] = Wih1[ga*64 + q];
        b1f[ga]  = bih1[ga*64 + q] + bhh1[ga*64 + q];
        b2f[ga]  = bih2[ga*64 + q] + bhh2[ga*64 + q];
    }
    u16* r1h = g_r1h + (size_t)blockIdx.x * TLEN * 2048;
    u16* r1l = g_r1l + (size_t)blockIdx.x * TLEN * 2048;

    // ---- stage weights ONCE (constant across steps) ----
    u32 Ahi1[4][4], Ahi2[8][4];
    #pragma unroll
    for (int kk = 0; kk < 4; kk++) {
        int k1 = 16*kk + 2*tg, k2 = k1 + 8;
        float2 vA1 = *(const float2*)(Whh1 + rowA*64 + k1);
        float2 vB1 = *(const float2*)(Whh1 + (rowA+128)*64 + k1);
        float2 vA2 = *(const float2*)(Whh1 + rowA*64 + k2);
        float2 vB2 = *(const float2*)(Whh1 + (rowA+128)*64 + k2);
        u32 lo[4];
        splitpack2(vA1.x, vA1.y, Ahi1[kk][0], lo[0]);
        splitpack2(vB1.x, vB1.y, Ahi1[kk][1], lo[1]);
        splitpack2(vA2.x, vA2.y, Ahi1[kk][2], lo[2]);
        splitpack2(vB2.x, vB2.y, Ahi1[kk][3], lo[3]);
        *(uint4*)(alo1s + (kk*512 + tid)*4) = make_uint4(lo[0], lo[1], lo[2], lo[3]);
    }
    #pragma unroll
    for (int kk = 0; kk < 8; kk++) {
        const float* W = (kk < 4) ? Wih2 : Whh2;
        int k1 = 16*(kk & 3) + 2*tg, k2 = k1 + 8;
        float2 vA1 = *(const float2*)(W + rowA*64 + k1);
        float2 vB1 = *(const float2*)(W + (rowA+128)*64 + k1);
        float2 vA2 = *(const float2*)(W + rowA*64 + k2);
        float2 vB2 = *(const float2*)(W + (rowA+128)*64 + k2);
        u32 lo[4];
        splitpack2(vA1.x, vA1.y, Ahi2[kk][0], lo[0]);
        splitpack2(vB1.x, vB1.y, Ahi2[kk][1], lo[1]);
        splitpack2(vA2.x, vA2.y, Ahi2[kk][2], lo[2]);
        splitpack2(vB2.x, vB2.y, Ahi2[kk][3], lo[3]);
        *(uint4*)(alo2s + (kk*512 + tid)*4) = make_uint4(lo[0], lo[1], lo[2], lo[3]);
    }

    float cst1[4], cst2[4], hl1[4];
    u32 r1nh0 = 0, r1nh1 = 0, r1nl0 = 0, r1nl1 = 0;
    __syncthreads();

    // ===== fused pipeline: super s runs layer1(step s) + layer2(step s-1) =====
    for (int s = 0; s <= NSTEPS; s++) {
        const bool doL1 = (s < NSTEPS);
        const bool doL2 = (s > 0);

        // ---- super boundary ----
        if (doL2) {
            #pragma unroll
            for (int j = 0; j < 4; j++) cst2[j] = cst1[j];   // c2_0 = c1_T
            char* h0 = sm + OFF_H2;                           // H2 buf0
            u32 hA, lA, hB, lB;
            splitpack2(hl1[0], hl1[1], hA, lA);
            splitpack2(hl1[2], hl1[3], hB, lB);
            *(u32*)(h0 + (64+q)*PB + 2*bb0)       = hA;       // h2_0 = h1_T
            *(u32*)(h0 + (64+q)*PB + 2*bb0 + 16)  = hB;
            *(u32*)(h0 + (192+q)*PB + 2*bb0)      = lA;
            *(u32*)(h0 + (192+q)*PB + 2*bb0 + 16) = lB;
            size_t ri = (size_t)q*32 + bb0;                   // r1(s-1, 0)
            *(u32*)(h0 + q*PB + 2*bb0)            = *(const u32*)(r1h + ri);
            *(u32*)(h0 + q*PB + 2*bb0 + 16)       = *(const u32*)(r1h + ri + 8);
            *(u32*)(h0 + (128+q)*PB + 2*bb0)      = *(const u32*)(r1l + ri);
            *(u32*)(h0 + (128+q)*PB + 2*bb0 + 16) = *(const u32*)(r1l + ri + 8);
            r1nh0 = *(const u32*)(r1h + 2048 + ri);           // prefetch r1(s-1, 1)
            r1nh1 = *(const u32*)(r1h + 2048 + ri + 8);
            r1nl0 = *(const u32*)(r1l + 2048 + ri);
            r1nl1 = *(const u32*)(r1l + 2048 + ri + 8);
        }
        if (doL1) {
            for (int i = tid; i < H1B/4; i += NTHR)           // zero H1 buf0
                ((u32*)(sm + OFF_H1))[i] = 0u;
            #pragma unroll
            for (int j = 0; j < 4; j++) cst1[j] = 0.0f;
        }
        __syncthreads();

        // ---- phase loop: L2 at t2=p, FC at p=168, L1 at t1=p-2 ----
        for (int p = 0; p < TLEN + 2; p++) {
            if (doL2 && p < TLEN) {
                const int t2 = p;
                float cP[4][4], cQ[4][4];
                #pragma unroll
                for (int n = 0; n < 4; n++)
                    #pragma unroll
                    for (int j = 0; j < 4; j++) { cP[n][j] = 0.0f; cQ[n][j] = 0.0f; }
                do_mma<8,128>(hsm2 + (t2&1)*H2B + laneoff, alo2, Ahi2, cP, cQ);
                float c[4][4];
                #pragma unroll
                for (int n = 0; n < 4; n++)
                    #pragma unroll
                    for (int j = 0; j < 4; j++) c[n][j] = cP[n][j] + cQ[n][j];
                float rx[2][4];
                #pragma unroll
                for (int n2 = 0; n2 < 2; n2++)
                    #pragma unroll
                    for (int j = 0; j < 4; j++) {
                        float send = glo ? c[2+n2][j] : c[n2][j];
                        rx[n2][j] = __shfl_xor_sync(0xffffffffu, send, 16);
                    }
                float hcur[4];
                #pragma unroll
                for (int j = 0; j < 4; j++) {
                    int n2 = j >> 1, col = j & 1;
                    float gi = (glo ? c[n2][col]    : rx[n2][col])    + b2f[0];
                    float f  = (glo ? rx[n2][col]   : c[2+n2][col])   + b2f[1];
                    float gg = (glo ? c[n2][2+col]  : rx[n2][2+col])  + b2f[2];
                    float o  = (glo ? rx[n2][2+col] : c[2+n2][2+col]) + b2f[3];
                    float cn = fmaf(sigf(f), cst2[j], sigf(gi)*tanhf_(gg));
                    cst2[j] = cn;
                    hcur[j] = sigf(o)*tanhf_(cn);
                }
                if (t2 + 1 < TLEN) {
                    u32 hA, lA, hB, lB;
                    splitpack2(hcur[0], hcur[1], hA, lA);
                    splitpack2(hcur[2], hcur[3], hB, lB);
                    char* hw = sm + OFF_H2 + ((t2+1)&1)*H2B;
                    *(u32*)(hw + (64+q)*PB + 2*bb0)       = hA;
                    *(u32*)(hw + (64+q)*PB + 2*bb0 + 16)  = hB;
                    *(u32*)(hw + (192+q)*PB + 2*bb0)      = lA;
                    *(u32*)(hw + (192+q)*PB + 2*bb0 + 16) = lB;
                    *(u32*)(hw + q*PB + 2*bb0)            = r1nh0;
                    *(u32*)(hw + q*PB + 2*bb0 + 16)       = r1nh1;
                    *(u32*)(hw + (128+q)*PB + 2*bb0)      = r1nl0;
                    *(u32*)(hw + (128+q)*PB + 2*bb0 + 16) = r1nl1;
                    if (t2 + 2 < TLEN) {
                        size_t ri = (size_t)(t2+2)*2048 + q*32 + bb0;
                        r1nh0 = *(const u32*)(r1h + ri);
                        r1nh1 = *(const u32*)(r1h + ri + 8);
                        r1nl0 = *(const u32*)(r1l + ri);
                        r1nl1 = *(const u32*)(r1l + ri + 8);
                    }
                } else {
                    *(float2*)(scr + q*32 + bb0)     = make_float2(fmaxf(hcur[0],0.0f), fmaxf(hcur[1],0.0f));
                    *(float2*)(scr + q*32 + bb0 + 8) = make_float2(fmaxf(hcur[2],0.0f), fmaxf(hcur[3],0.0f));
                }
            }
            if (doL2 && p == TLEN && tid < 32) {
                float sfc = *bcs + wcomb[64] * dsh[tid];
                #pragma unroll
                for (int uu = 0; uu < 64; uu++)
                    sfc = fmaf(wcomb[uu], scr[uu*32 + tid], sfc);
                out[(size_t)(b0g + tid)*NSTEPS + (s-1)] = sfc;
                win[(TLEN + s - 1)*32 + tid] = sfc;
            }
            if (doL1 && p >= 2) {
                const int t1 = p - 2;
                float cP[4][4], cQ[4][4];
                #pragma unroll
                for (int n = 0; n < 4; n++)
                    #pragma unroll
                    for (int j = 0; j < 4; j++) { cP[n][j] = 0.0f; cQ[n][j] = 0.0f; }
                do_mma<4,64>(hsm1 + (t1&1)*H1B + laneoff, alo1, Ahi1, cP, cQ);
                float c[4][4];
                #pragma unroll
                for (int n = 0; n < 4; n++)
                    #pragma unroll
                    for (int j = 0; j < 4; j++) c[n][j] = cP[n][j] + cQ[n][j];
                float rx[2][4];
                #pragma unroll
                for (int n2 = 0; n2 < 2; n2++)
                    #pragma unroll
                    for (int j = 0; j < 4; j++) {
                        float send = glo ? c[2+n2][j] : c[n2][j];
                        rx[n2][j] = __shfl_xor_sync(0xffffffffu, send, 16);
                    }
                float2 xv0 = *(const float2*)(win + (s+t1)*32 + bb0);
                float2 xv1 = *(const float2*)(win + (s+t1)*32 + bb0 + 8);
                float xa[4] = {xv0.x, xv0.y, xv1.x, xv1.y};
                #pragma unroll
                for (int j = 0; j < 4; j++) {
                    int n2 = j >> 1, col = j & 1;
                    float gi = glo ? c[n2][col]     : rx[n2][col];
                    float gg = glo ? c[n2][2+col]   : rx[n2][2+col];
                    float f  = glo ? rx[n2][col]    : c[2+n2][col];
                    float o  = glo ? rx[n2][2+col]  : c[2+n2][2+col];
                    gi += fmaf(xa[j], wi1f[0], b1f[0]);
                    f  += fmaf(xa[j], wi1f[1], b1f[1]);
                    gg += fmaf(xa[j], wi1f[2], b1f[2]);
                    o  += fmaf(xa[j], wi1f[3], b1f[3]);
                    float cn = fmaf(sigf(f), cst1[j], sigf(gi)*tanhf_(gg));
                    cst1[j] = cn;
                    hl1[j] = sigf(o)*tanhf_(cn);
                }
                u32 hA, lA, hB, lB, rhA, rlA, rhB, rlB;
                splitpack2(hl1[0], hl1[1], hA, lA);
                splitpack2(hl1[2], hl1[3], hB, lB);
                splitpack2(fmaxf(hl1[0],0.0f), fmaxf(hl1[1],0.0f), rhA, rlA);
                splitpack2(fmaxf(hl1[2],0.0f), fmaxf(hl1[3],0.0f), rhB, rlB);
                char* hw = sm + OFF_H1 + ((t1+1)&1)*H1B;
                *(u32*)(hw + q*PB + 2*bb0)           = hA;
                *(u32*)(hw + q*PB + 2*bb0 + 16)      = hB;
                *(u32*)(hw + (64+q)*PB + 2*bb0)      = lA;
                *(u32*)(hw + (64+q)*PB + 2*bb0 + 16) = lB;
                size_t ri = (size_t)t1*2048 + q*32 + bb0;
                *(u32*)(r1h + ri)     = rhA;
                *(u32*)(r1h + ri + 8) = rhB;
                *(u32*)(r1l + ri)     = rlA;
                *(u32*)(r1l + ri + 8) = rlB;
            }
            __syncthreads();
        }
    }
}

extern "C" void kernel_launch(void* const* d_in, const int* in_sizes, int n_in,
                              void* d_out, int out_size) {
    (void)in_sizes; (void)n_in; (void)out_size;
    const float* x    = (const float*)d_in[0];
    const float* Wih1 = (const float*)d_in[1];
    const float* Whh1 = (const float*)d_in[2];
    const float* bih1 = (const float*)d_in[3];
    const float* bhh1 = (const float*)d_in[4];
    const float* Wih2 = (const float*)d_in[5];
    const float* Whh2 = (const float*)d_in[6];
    const float* bih2 = (const float*)d_in[7];
    const float* bhh2 = (const float*)d_in[8];
    const float* fc1w = (const float*)d_in[9];
    const float* fc1b = (const float*)d_in[10];
    const float* fc2w = (const float*)d_in[11];
    const float* fc2b = (const float*)d_in[12];
    float* out = (float*)d_out;

    cudaFuncSetAttribute(lstm_rec_kernel, cudaFuncAttributeMaxDynamicSharedMemorySize, SMEM_BYTES);
    lstm_rec_kernel<<<GRID, NTHR, SMEM_BYTES>>>(x, Wih1, Whh1, bih1, bhh1,
                                                Wih2, Whh2, bih2, bhh2,
                                                fc1w, fc1b, fc2w, fc2b, out);
}

// round 16
// speedup vs baseline: 1.4383x; 1.4383x over previous
#include <cuda_runtime.h>
#include <cuda_fp16.h>

typedef unsigned int u32;
typedef unsigned short u16;
typedef unsigned long long u64;

#define GRID   128
#define NTHR   512
#define TLEN   168
#define SEQ    169
#define NSTEPS 24
#define PB     80                 // H row pitch in bytes
#define HBUFB  (128 * PB)         // one H buffer: 128 k-rows, single fp16 plane

#define OFF_H    0
#define OFF_ALO1 (2 * HBUFB)                 // 20480: Wlo1 frags 4kk x 512 x 16B = 32KB
#define OFF_ALO2 (OFF_ALO1 + 32768)          // 53248: Wlo2 frags 8kk x 512 x 16B = 64KB
#define OFF_WIN  (OFF_ALO2 + 65536)          // 118784
#define OFF_SCR  (OFF_WIN + 192*32*4)        // 143360
#define OFF_MISC (OFF_SCR + 64*32*4)         // 151552
#define SMEM_BYTES (OFF_MISC + 512)          // 152064

#define WLO_INV 0.0009765625f     // 1/1024

// r1 staging, single fp16 plane: [GRID][TLEN][64 units][32 batches]
__device__ u16 g_r1[(size_t)GRID * TLEN * 64 * 32];

static __device__ __forceinline__ float rcpf(float x){float r;asm("rcp.approx.f32 %0,%1;":"=f"(r):"f"(x));return r;}
static __device__ __forceinline__ float sigf(float x){return rcpf(1.0f+__expf(-x));}
static __device__ __forceinline__ float tanhf_(float x){return fmaf(2.0f,sigf(2.0f*x),-1.0f);}

// pack two floats to fp16x2 (x0 in low half)
static __device__ __forceinline__ u32 packh2(float x0,float x1){
    u32 d;asm("cvt.rn.f16x2.f32 %0,%1,%2;":"=r"(d):"f"(x1),"f"(x0));return d;
}
// W split: hi = fp16 pair, lo = fp16 pair of (residual * 1024)
static __device__ __forceinline__ void wsplit2(float x0,float x1,u32&hi,u32&lo){
    __half h0=__float2half_rn(x0), h1=__float2half_rn(x1);
    u16 u0=__half_as_ushort(h0), u1=__half_as_ushort(h1);
    hi=(u32)u0|((u32)u1<<16);
    float r0=(x0-__half2float(h0))*1024.0f;
    float r1=(x1-__half2float(h1))*1024.0f;
    lo=packh2(r0,r1);
}
static __device__ __forceinline__ void mma4(float c[4],const u32 a[4],u32 b0,u32 b1){
    asm volatile("mma.sync.aligned.m16n8k16.row.col.f32.f16.f16.f32 "
        "{%0,%1,%2,%3},{%4,%5,%6,%7},{%8,%9},{%0,%1,%2,%3};"
        :"+f"(c[0]),"+f"(c[1]),"+f"(c[2]),"+f"(c[3])
        :"r"(a[0]),"r"(a[1]),"r"(a[2]),"r"(a[3]),"r"(b0),"r"(b1));
}
static __device__ __forceinline__ void ldm4t(u32 addr,u32&r0,u32&r1,u32&r2,u32&r3){
    asm volatile("ldmatrix.sync.aligned.m8n8.x4.trans.shared.b16 {%0,%1,%2,%3}, [%4];"
        :"=r"(r0),"=r"(r1),"=r"(r2),"=r"(r3):"r"(addr));
}
static __device__ __forceinline__ void lds128(u32 addr,u32 r[4]){
    asm volatile("ld.shared.v4.u32 {%0,%1,%2,%3}, [%4];"
        :"=r"(r[0]),"=r"(r[1]),"=r"(r[2]),"=r"(r[3]):"r"(addr));
}

// 2-pass fp16 split GEMM: cP += Whi*H ; cQ += (Wlo*1024)*H
template<int KK>
static __device__ __forceinline__ void do_mma(u32 hb, u32 alo0,
                                              const u32 Ahi[][4],
                                              float cP[4][4], float cQ[4][4])
{
    #pragma unroll
    for (int kk = 0; kk < KK; kk++) {
        u32 a0 = hb + (u32)(kk * 16 * PB);
        u32 al[4];
        lds128(alo0 + (u32)(kk * 8192), al);
        u32 b0,b1,b2,b3,b4,b5,b6,b7;
        ldm4t(a0,    b0,b1,b2,b3);
        ldm4t(a0+32, b4,b5,b6,b7);
        mma4(cP[0], Ahi[kk], b0, b1);
        mma4(cP[1], Ahi[kk], b2, b3);
        mma4(cP[2], Ahi[kk], b4, b5);
        mma4(cP[3], Ahi[kk], b6, b7);
        mma4(cQ[0], al, b0, b1);
        mma4(cQ[1], al, b2, b3);
        mma4(cQ[2], al, b4, b5);
        mma4(cQ[3], al, b6, b7);
    }
}

__global__ void __launch_bounds__(NTHR, 1)
lstm_rec_kernel(const float* __restrict__ x,
                const float* __restrict__ Wih1, const float* __restrict__ Whh1,
                const float* __restrict__ bih1, const float* __restrict__ bhh1,
                const float* __restrict__ Wih2, const float* __restrict__ Whh2,
                const float* __restrict__ bih2, const float* __restrict__ bhh2,
                const float* __restrict__ fc1w, const float* __restrict__ fc1b,
                const float* __restrict__ fc2w, const float* __restrict__ fc2b,
                float* __restrict__ out)
{
    extern __shared__ char sm[];
    float* win   = (float*)(sm + OFF_WIN);   // [192][32] t-major
    float* scr   = (float*)(sm + OFF_SCR);   // [64][32]
    float* wcomb = (float*)(sm + OFF_MISC);  // [65]
    float* bcs   = wcomb + 65;
    float* dsh   = wcomb + 66;               // [32]
    u32*   alo1s = (u32*)(sm + OFF_ALO1);
    u32*   alo2s = (u32*)(sm + OFF_ALO2);

    const int tid  = threadIdx.x;
    const int b0g  = blockIdx.x * 32;
    const int warp = tid >> 5, lane = tid & 31;
    const int g    = lane >> 2, tg = lane & 3;
    const int q    = 4*warp + (g & 3);                 // this thread's unit
    const bool glo = (g < 4);
    const int bb0  = (glo ? 0 : 16) + 2*tg;            // batches bb0,bb0+1,bb0+8,bb0+9
    const int rowA = (g >> 2)*64 + 4*warp + (g & 3);   // W row for C-tile row g

    const u32 hsm0 = (u32)__cvta_generic_to_shared(sm + OFF_H);
    const u32 alo1 = (u32)__cvta_generic_to_shared(alo1s) + (u32)tid * 16;
    const u32 alo2 = (u32)__cvta_generic_to_shared(alo2s) + (u32)tid * 16;
    const u32 laneoff = (u32)((lane & 7) * PB + ((lane >> 3) & 1) * (8 * PB) + (lane >> 4) * 16);

    // ---- one-time init ----
    for (int i = tid; i < TLEN*32; i += NTHR) {
        int t = i >> 5, b = i & 31;
        win[t*32 + b] = x[(size_t)(b0g + b)*SEQ + t];
    }
    if (tid < 32) dsh[tid] = x[(size_t)(b0g + tid)*SEQ + TLEN];
    if (tid < 65) {
        float s = 0.0f;
        for (int j = 0; j < 64; j++) s = fmaf(fc2w[j], fc1w[j*65 + tid], s);
        wcomb[tid] = s;
    }
    if (tid == 65) {
        float s = fc2b[0];
        for (int j = 0; j < 64; j++) s = fmaf(fc2w[j], fc1b[j], s);
        *bcs = s;
    }
    float wi1f[4], b1f[4], b2f[4];
    #pragma unroll
    for (int ga = 0; ga < 4; ga++) {
        wi1f[ga] = Wih1[ga*64 + q];
        b1f[ga]  = bih1[ga*64 + q] + bhh1[ga*64 + q];
        b2f[ga]  = bih2[ga*64 + q] + bhh2[ga*64 + q];
    }
    u16* r1p = g_r1 + (size_t)blockIdx.x * TLEN * 2048;

    // ---- stage weights ONCE (constant across steps) ----
    u32 Ahi1[4][4], Ahi2[8][4];
    #pragma unroll
    for (int kk = 0; kk < 4; kk++) {
        int k1 = 16*kk + 2*tg, k2 = k1 + 8;
        float2 vA1 = *(const float2*)(Whh1 + rowA*64 + k1);
        float2 vB1 = *(const float2*)(Whh1 + (rowA+128)*64 + k1);
        float2 vA2 = *(const float2*)(Whh1 + rowA*64 + k2);
        float2 vB2 = *(const float2*)(Whh1 + (rowA+128)*64 + k2);
        u32 lo[4];
        wsplit2(vA1.x, vA1.y, Ahi1[kk][0], lo[0]);
        wsplit2(vB1.x, vB1.y, Ahi1[kk][1], lo[1]);
        wsplit2(vA2.x, vA2.y, Ahi1[kk][2], lo[2]);
        wsplit2(vB2.x, vB2.y, Ahi1[kk][3], lo[3]);
        *(uint4*)(alo1s + (kk*512 + tid)*4) = make_uint4(lo[0], lo[1], lo[2], lo[3]);
    }
    #pragma unroll
    for (int kk = 0; kk < 8; kk++) {
        const float* W = (kk < 4) ? Wih2 : Whh2;
        int k1 = 16*(kk & 3) + 2*tg, k2 = k1 + 8;
        float2 vA1 = *(const float2*)(W + rowA*64 + k1);
        float2 vB1 = *(const float2*)(W + (rowA+128)*64 + k1);
        float2 vA2 = *(const float2*)(W + rowA*64 + k2);
        float2 vB2 = *(const float2*)(W + (rowA+128)*64 + k2);
        u32 lo[4];
        wsplit2(vA1.x, vA1.y, Ahi2[kk][0], lo[0]);
        wsplit2(vB1.x, vB1.y, Ahi2[kk][1], lo[1]);
        wsplit2(vA2.x, vA2.y, Ahi2[kk][2], lo[2]);
        wsplit2(vB2.x, vB2.y, Ahi2[kk][3], lo[3]);
        *(uint4*)(alo2s + (kk*512 + tid)*4) = make_uint4(lo[0], lo[1], lo[2], lo[3]);
    }

    float cst[4], hl[4];
    u32 r1n0 = 0, r1n1 = 0;
    __syncthreads();

    for (int step = 0; step < NSTEPS; step++) {
        // ---- zero H buf0 rows 0-63 (h1(0)=0); reset c ----
        for (int i = tid; i < (64*PB)/4; i += NTHR) ((u32*)(sm + OFF_H))[i] = 0u;
        cst[0] = cst[1] = cst[2] = cst[3] = 0.0f;
        __syncthreads();

        // ================= layer 1 =================
        for (int t = 0; t < TLEN; t++) {
            float cP[4][4], cQ[4][4];
            #pragma unroll
            for (int n = 0; n < 4; n++)
                #pragma unroll
                for (int j = 0; j < 4; j++) { cP[n][j] = 0.0f; cQ[n][j] = 0.0f; }
            do_mma<4>(hsm0 + (t&1)*HBUFB + laneoff, alo1, Ahi1, cP, cQ);
            float c[4][4];
            #pragma unroll
            for (int n = 0; n < 4; n++)
                #pragma unroll
                for (int j = 0; j < 4; j++) c[n][j] = fmaf(cQ[n][j], WLO_INV, cP[n][j]);
            float rx[2][4];
            #pragma unroll
            for (int n2 = 0; n2 < 2; n2++)
                #pragma unroll
                for (int j = 0; j < 4; j++) {
                    float send = glo ? c[2+n2][j] : c[n2][j];
                    rx[n2][j] = __shfl_xor_sync(0xffffffffu, send, 16);
                }
            float2 xv0 = *(const float2*)(win + (step+t)*32 + bb0);
            float2 xv1 = *(const float2*)(win + (step+t)*32 + bb0 + 8);
            float xa[4] = {xv0.x, xv0.y, xv1.x, xv1.y};
            #pragma unroll
            for (int j = 0; j < 4; j++) {
                int n2 = j >> 1, col = j & 1;
                float gi = glo ? c[n2][col]     : rx[n2][col];
                float gg = glo ? c[n2][2+col]   : rx[n2][2+col];
                float f  = glo ? rx[n2][col]    : c[2+n2][col];
                float o  = glo ? rx[n2][2+col]  : c[2+n2][2+col];
                gi += fmaf(xa[j], wi1f[0], b1f[0]);
                f  += fmaf(xa[j], wi1f[1], b1f[1]);
                gg += fmaf(xa[j], wi1f[2], b1f[2]);
                o  += fmaf(xa[j], wi1f[3], b1f[3]);
                float cn = fmaf(sigf(f), cst[j], sigf(gi)*tanhf_(gg));
                cst[j] = cn;
                hl[j] = sigf(o)*tanhf_(cn);
            }
            char* hw = sm + OFF_H + ((t+1)&1)*HBUFB;
            *(u32*)(hw + q*PB + 2*bb0)      = packh2(hl[0], hl[1]);
            *(u32*)(hw + q*PB + 2*bb0 + 16) = packh2(hl[2], hl[3]);
            size_t ri = (size_t)t*2048 + q*32 + bb0;
            *(u32*)(r1p + ri)     = packh2(fmaxf(hl[0],0.0f), fmaxf(hl[1],0.0f));
            *(u32*)(r1p + ri + 8) = packh2(fmaxf(hl[2],0.0f), fmaxf(hl[3],0.0f));
            __syncthreads();
        }

        // ---- transition into buf0: rows 64+q = h1_T, rows q = r1(0); prefetch r1(1) ----
        {
            char* h0 = sm + OFF_H;
            *(u32*)(h0 + (64+q)*PB + 2*bb0)      = packh2(hl[0], hl[1]);
            *(u32*)(h0 + (64+q)*PB + 2*bb0 + 16) = packh2(hl[2], hl[3]);
            size_t ri = (size_t)q*32 + bb0;
            *(u32*)(h0 + q*PB + 2*bb0)      = *(const u32*)(r1p + ri);
            *(u32*)(h0 + q*PB + 2*bb0 + 16) = *(const u32*)(r1p + ri + 8);
            r1n0 = *(const u32*)(r1p + 2048 + ri);
            r1n1 = *(const u32*)(r1p + 2048 + ri + 8);
        }
        __syncthreads();

        // ================= layer 2 =================
        for (int t = 0; t < TLEN; t++) {
            float cP[4][4], cQ[4][4];
            #pragma unroll
            for (int n = 0; n < 4; n++)
                #pragma unroll
                for (int j = 0; j < 4; j++) { cP[n][j] = 0.0f; cQ[n][j] = 0.0f; }
            do_mma<8>(hsm0 + (t&1)*HBUFB + laneoff, alo2, Ahi2, cP, cQ);
            float c[4][4];
            #pragma unroll
            for (int n = 0; n < 4; n++)
                #pragma unroll
                for (int j = 0; j < 4; j++) c[n][j] = fmaf(cQ[n][j], WLO_INV, cP[n][j]);
            float rx[2][4];
            #pragma unroll
            for (int n2 = 0; n2 < 2; n2++)
                #pragma unroll
                for (int j = 0; j < 4; j++) {
                    float send = glo ? c[2+n2][j] : c[n2][j];
                    rx[n2][j] = __shfl_xor_sync(0xffffffffu, send, 16);
                }
            float hcur[4];
            #pragma unroll
            for (int j = 0; j < 4; j++) {
                int n2 = j >> 1, col = j & 1;
                float gi = (glo ? c[n2][col]    : rx[n2][col])    + b2f[0];
                float f  = (glo ? rx[n2][col]   : c[2+n2][col])   + b2f[1];
                float gg = (glo ? c[n2][2+col]  : rx[n2][2+col])  + b2f[2];
                float o  = (glo ? rx[n2][2+col] : c[2+n2][2+col]) + b2f[3];
                float cn = fmaf(sigf(f), cst[j], sigf(gi)*tanhf_(gg));
                cst[j] = cn;
                hcur[j] = sigf(o)*tanhf_(cn);
            }
            if (t + 1 < TLEN) {
                char* hw = sm + OFF_H + ((t+1)&1)*HBUFB;
                *(u32*)(hw + (64+q)*PB + 2*bb0)      = packh2(hcur[0], hcur[1]);
                *(u32*)(hw + (64+q)*PB + 2*bb0 + 16) = packh2(hcur[2], hcur[3]);
                *(u32*)(hw + q*PB + 2*bb0)           = r1n0;
                *(u32*)(hw + q*PB + 2*bb0 + 16)      = r1n1;
                if (t + 2 < TLEN) {
                    size_t ri = (size_t)(t+2)*2048 + q*32 + bb0;
                    r1n0 = *(const u32*)(r1p + ri);
                    r1n1 = *(const u32*)(r1p + ri + 8);
                }
            } else {
                *(float2*)(scr + q*32 + bb0)     = make_float2(fmaxf(hcur[0],0.0f), fmaxf(hcur[1],0.0f));
                *(float2*)(scr + q*32 + bb0 + 8) = make_float2(fmaxf(hcur[2],0.0f), fmaxf(hcur[3],0.0f));
            }
            __syncthreads();
        }

        // ---- FC (collapsed) + window append ----
        if (tid < 32) {
            float s = *bcs + wcomb[64] * dsh[tid];
            #pragma unroll
            for (int uu = 0; uu < 64; uu++)
                s = fmaf(wcomb[uu], scr[uu*32 + tid], s);
            out[(size_t)(b0g + tid)*NSTEPS + step] = s;
            win[(TLEN + step)*32 + tid] = s;
        }
        __syncthreads();
    }
}

extern "C" void kernel_launch(void* const* d_in, const int* in_sizes, int n_in,
                              void* d_out, int out_size) {
    (void)in_sizes; (void)n_in; (void)out_size;
    const float* x    = (const float*)d_in[0];
    const float* Wih1 = (const float*)d_in[1];
    const float* Whh1 = (const float*)d_in[2];
    const float* bih1 = (const float*)d_in[3];
    const float* bhh1 = (const float*)d_in[4];
    const float* Wih2 = (const float*)d_in[5];
    const float* Whh2 = (const float*)d_in[6];
    const float* bih2 = (const float*)d_in[7];
    const float* bhh2 = (const float*)d_in[8];
    const float* fc1w = (const float*)d_in[9];
    const float* fc1b = (const float*)d_in[10];
    const float* fc2w = (const float*)d_in[11];
    const float* fc2b = (const float*)d_in[12];
    float* out = (float*)d_out;

    cudaFuncSetAttribute(lstm_rec_kernel, cudaFuncAttributeMaxDynamicSharedMemorySize, SMEM_BYTES);
    lstm_rec_kernel<<<GRID, NTHR, SMEM_BYTES>>>(x, Wih1, Whh1, bih1, bhh1,
                                                Wih2, Whh2, bih2, bhh2,
                                                fc1w, fc1b, fc2w, fc2b, out);
}

// round 17
// speedup vs baseline: 1.9085x; 1.3269x over previous
#include <cuda_runtime.h>
#include <cuda_fp16.h>

typedef unsigned int u32;
typedef unsigned short u16;
typedef unsigned long long u64;

#define GRID   128
#define NTHR   512
#define TLEN   168
#define SEQ    169
#define NSTEPS 24
#define PB     80                 // H row pitch in bytes
#define HBUFB  (128 * PB)         // one H buffer: 128 k-rows, single fp16 plane

#define OFF_H    0
#define OFF_WIN  (2 * HBUFB)                 // 20480
#define OFF_SCR  (OFF_WIN + 192*32*4)        // 45056
#define OFF_MISC (OFF_SCR + 64*32*4)         // 53248
#define SMEM_BYTES (OFF_MISC + 512)          // 53760

// r1 staging, single fp16 plane: [GRID][TLEN][64 units][32 batches]
__device__ u16 g_r1[(size_t)GRID * TLEN * 64 * 32];

static __device__ __forceinline__ float rcpf(float x){float r;asm("rcp.approx.f32 %0,%1;":"=f"(r):"f"(x));return r;}
static __device__ __forceinline__ float sigf(float x){return rcpf(1.0f+__expf(-x));}
static __device__ __forceinline__ float tanhf_(float x){return fmaf(2.0f,sigf(2.0f*x),-1.0f);}

// pack two floats to fp16x2 (x0 in low half)
static __device__ __forceinline__ u32 packh2(float x0,float x1){
    u32 d;asm("cvt.rn.f16x2.f32 %0,%1,%2;":"=r"(d):"f"(x1),"f"(x0));return d;
}
static __device__ __forceinline__ void mma4(float c[4],const u32 a[4],u32 b0,u32 b1){
    asm volatile("mma.sync.aligned.m16n8k16.row.col.f32.f16.f16.f32 "
        "{%0,%1,%2,%3},{%4,%5,%6,%7},{%8,%9},{%0,%1,%2,%3};"
        :"+f"(c[0]),"+f"(c[1]),"+f"(c[2]),"+f"(c[3])
        :"r"(a[0]),"r"(a[1]),"r"(a[2]),"r"(a[3]),"r"(b0),"r"(b1));
}
static __device__ __forceinline__ void ldm4t(u32 addr,u32&r0,u32&r1,u32&r2,u32&r3){
    asm volatile("ldmatrix.sync.aligned.m8n8.x4.trans.shared.b16 {%0,%1,%2,%3}, [%4];"
        :"=r"(r0),"=r"(r1),"=r"(r2),"=r"(r3):"r"(addr));
}

// single-pass fp16 GEMM
template<int KK>
static __device__ __forceinline__ void do_mma(u32 hb,
                                              const u32 Ahi[][4],
                                              float c[4][4])
{
    #pragma unroll
    for (int kk = 0; kk < KK; kk++) {
        u32 a0 = hb + (u32)(kk * 16 * PB);
        u32 b0,b1,b2,b3,b4,b5,b6,b7;
        ldm4t(a0,    b0,b1,b2,b3);
        ldm4t(a0+32, b4,b5,b6,b7);
        mma4(c[0], Ahi[kk], b0, b1);
        mma4(c[1], Ahi[kk], b2, b3);
        mma4(c[2], Ahi[kk], b4, b5);
        mma4(c[3], Ahi[kk], b6, b7);
    }
}

__global__ void __launch_bounds__(NTHR, 1)
lstm_rec_kernel(const float* __restrict__ x,
                const float* __restrict__ Wih1, const float* __restrict__ Whh1,
                const float* __restrict__ bih1, const float* __restrict__ bhh1,
                const float* __restrict__ Wih2, const float* __restrict__ Whh2,
                const float* __restrict__ bih2, const float* __restrict__ bhh2,
                const float* __restrict__ fc1w, const float* __restrict__ fc1b,
                const float* __restrict__ fc2w, const float* __restrict__ fc2b,
                float* __restrict__ out)
{
    extern __shared__ char sm[];
    float* win   = (float*)(sm + OFF_WIN);   // [192][32] t-major
    float* scr   = (float*)(sm + OFF_SCR);   // [64][32]
    float* wcomb = (float*)(sm + OFF_MISC);  // [65]
    float* bcs   = wcomb + 65;
    float* dsh   = wcomb + 66;               // [32]

    const int tid  = threadIdx.x;
    const int b0g  = blockIdx.x * 32;
    const int warp = tid >> 5, lane = tid & 31;
    const int g    = lane >> 2, tg = lane & 3;
    const int q    = 4*warp + (g & 3);                 // this thread's unit
    const bool glo = (g < 4);
    const int bb0  = (glo ? 0 : 16) + 2*tg;            // batches bb0,bb0+1,bb0+8,bb0+9
    const int rowA = (g >> 2)*64 + 4*warp + (g & 3);   // W row for C-tile row g

    const u32 hsm0 = (u32)__cvta_generic_to_shared(sm + OFF_H);
    const u32 laneoff = (u32)((lane & 7) * PB + ((lane >> 3) & 1) * (8 * PB) + (lane >> 4) * 16);

    // ---- one-time init ----
    for (int i = tid; i < TLEN*32; i += NTHR) {
        int t = i >> 5, b = i & 31;
        win[t*32 + b] = x[(size_t)(b0g + b)*SEQ + t];
    }
    if (tid < 32) dsh[tid] = x[(size_t)(b0g + tid)*SEQ + TLEN];
    if (tid < 65) {
        float s = 0.0f;
        for (int j = 0; j < 64; j++) s = fmaf(fc2w[j], fc1w[j*65 + tid], s);
        wcomb[tid] = s;
    }
    if (tid == 65) {
        float s = fc2b[0];
        for (int j = 0; j < 64; j++) s = fmaf(fc2w[j], fc1b[j], s);
        *bcs = s;
    }
    float wi1f[4], b1f[4], b2f[4];
    #pragma unroll
    for (int ga = 0; ga < 4; ga++) {
        wi1f[ga] = Wih1[ga*64 + q];
        b1f[ga]  = bih1[ga*64 + q] + bhh1[ga*64 + q];
        b2f[ga]  = bih2[ga*64 + q] + bhh2[ga*64 + q];
    }
    u16* r1p = g_r1 + (size_t)blockIdx.x * TLEN * 2048;

    // ---- stage weights ONCE (fp16 hi only) ----
    u32 Ahi1[4][4], Ahi2[8][4];
    #pragma unroll
    for (int kk = 0; kk < 4; kk++) {
        int k1 = 16*kk + 2*tg, k2 = k1 + 8;
        float2 vA1 = *(const float2*)(Whh1 + rowA*64 + k1);
        float2 vB1 = *(const float2*)(Whh1 + (rowA+128)*64 + k1);
        float2 vA2 = *(const float2*)(Whh1 + rowA*64 + k2);
        float2 vB2 = *(const float2*)(Whh1 + (rowA+128)*64 + k2);
        Ahi1[kk][0] = packh2(vA1.x, vA1.y);
        Ahi1[kk][1] = packh2(vB1.x, vB1.y);
        Ahi1[kk][2] = packh2(vA2.x, vA2.y);
        Ahi1[kk][3] = packh2(vB2.x, vB2.y);
    }
    #pragma unroll
    for (int kk = 0; kk < 8; kk++) {
        const float* W = (kk < 4) ? Wih2 : Whh2;
        int k1 = 16*(kk & 3) + 2*tg, k2 = k1 + 8;
        float2 vA1 = *(const float2*)(W + rowA*64 + k1);
        float2 vB1 = *(const float2*)(W + (rowA+128)*64 + k1);
        float2 vA2 = *(const float2*)(W + rowA*64 + k2);
        float2 vB2 = *(const float2*)(W + (rowA+128)*64 + k2);
        Ahi2[kk][0] = packh2(vA1.x, vA1.y);
        Ahi2[kk][1] = packh2(vB1.x, vB1.y);
        Ahi2[kk][2] = packh2(vA2.x, vA2.y);
        Ahi2[kk][3] = packh2(vB2.x, vB2.y);
    }

    float cst[4], hl[4];
    u32 r1n0 = 0, r1n1 = 0;
    __syncthreads();

    for (int step = 0; step < NSTEPS; step++) {
        // ---- zero H buf0 rows 0-63 (h1(0)=0); reset c ----
        for (int i = tid; i < (64*PB)/4; i += NTHR) ((u32*)(sm + OFF_H))[i] = 0u;
        cst[0] = cst[1] = cst[2] = cst[3] = 0.0f;
        __syncthreads();

        // ================= layer 1 =================
        for (int t = 0; t < TLEN; t++) {
            float c[4][4];
            #pragma unroll
            for (int n = 0; n < 4; n++) { c[n][0]=c[n][1]=c[n][2]=c[n][3]=0.0f; }
            do_mma<4>(hsm0 + (t&1)*HBUFB + laneoff, Ahi1, c);
            float rx[2][4];
            #pragma unroll
            for (int n2 = 0; n2 < 2; n2++)
                #pragma unroll
                for (int j = 0; j < 4; j++) {
                    float send = glo ? c[2+n2][j] : c[n2][j];
                    rx[n2][j] = __shfl_xor_sync(0xffffffffu, send, 16);
                }
            float2 xv0 = *(const float2*)(win + (step+t)*32 + bb0);
            float2 xv1 = *(const float2*)(win + (step+t)*32 + bb0 + 8);
            float xa[4] = {xv0.x, xv0.y, xv1.x, xv1.y};
            #pragma unroll
            for (int j = 0; j < 4; j++) {
                int n2 = j >> 1, col = j & 1;
                float gi = glo ? c[n2][col]     : rx[n2][col];
                float gg = glo ? c[n2][2+col]   : rx[n2][2+col];
                float f  = glo ? rx[n2][col]    : c[2+n2][col];
                float o  = glo ? rx[n2][2+col]  : c[2+n2][2+col];
                gi += fmaf(xa[j], wi1f[0], b1f[0]);
                f  += fmaf(xa[j], wi1f[1], b1f[1]);
                gg += fmaf(xa[j], wi1f[2], b1f[2]);
                o  += fmaf(xa[j], wi1f[3], b1f[3]);
                float cn = fmaf(sigf(f), cst[j], sigf(gi)*tanhf_(gg));
                cst[j] = cn;
                hl[j] = sigf(o)*tanhf_(cn);
            }
            char* hw = sm + OFF_H + ((t+1)&1)*HBUFB;
            *(u32*)(hw + q*PB + 2*bb0)      = packh2(hl[0], hl[1]);
            *(u32*)(hw + q*PB + 2*bb0 + 16) = packh2(hl[2], hl[3]);
            size_t ri = (size_t)t*2048 + q*32 + bb0;
            *(u32*)(r1p + ri)     = packh2(fmaxf(hl[0],0.0f), fmaxf(hl[1],0.0f));
            *(u32*)(r1p + ri + 8) = packh2(fmaxf(hl[2],0.0f), fmaxf(hl[3],0.0f));
            __syncthreads();
        }

        // ---- transition into buf0: rows 64+q = h1_T, rows q = r1(0); prefetch r1(1) ----
        {
            char* h0 = sm + OFF_H;
            *(u32*)(h0 + (64+q)*PB + 2*bb0)      = packh2(hl[0], hl[1]);
            *(u32*)(h0 + (64+q)*PB + 2*bb0 + 16) = packh2(hl[2], hl[3]);
            size_t ri = (size_t)q*32 + bb0;
            *(u32*)(h0 + q*PB + 2*bb0)      = *(const u32*)(r1p + ri);
            *(u32*)(h0 + q*PB + 2*bb0 + 16) = *(const u32*)(r1p + ri + 8);
            r1n0 = *(const u32*)(r1p + 2048 + ri);
            r1n1 = *(const u32*)(r1p + 2048 + ri + 8);
        }
        __syncthreads();

        // ================= layer 2 =================
        for (int t = 0; t < TLEN; t++) {
            float c[4][4];
            #pragma unroll
            for (int n = 0; n < 4; n++) { c[n][0]=c[n][1]=c[n][2]=c[n][3]=0.0f; }
            do_mma<8>(hsm0 + (t&1)*HBUFB + laneoff, Ahi2, c);
            float rx[2][4];
            #pragma unroll
            for (int n2 = 0; n2 < 2; n2++)
                #pragma unroll
                for (int j = 0; j < 4; j++) {
                    float send = glo ? c[2+n2][j] : c[n2][j];
                    rx[n2][j] = __shfl_xor_sync(0xffffffffu, send, 16);
                }
            float hcur[4];
            #pragma unroll
            for (int j = 0; j < 4; j++) {
                int n2 = j >> 1, col = j & 1;
                float gi = (glo ? c[n2][col]    : rx[n2][col])    + b2f[0];
                float f  = (glo ? rx[n2][col]   : c[2+n2][col])   + b2f[1];
                float gg = (glo ? c[n2][2+col]  : rx[n2][2+col])  + b2f[2];
                float o  = (glo ? rx[n2][2+col] : c[2+n2][2+col]) + b2f[3];
                float cn = fmaf(sigf(f), cst[j], sigf(gi)*tanhf_(gg));
                cst[j] = cn;
                hcur[j] = sigf(o)*tanhf_(cn);
            }
            if (t + 1 < TLEN) {
                char* hw = sm + OFF_H + ((t+1)&1)*HBUFB;
                *(u32*)(hw + (64+q)*PB + 2*bb0)      = packh2(hcur[0], hcur[1]);
                *(u32*)(hw + (64+q)*PB + 2*bb0 + 16) = packh2(hcur[2], hcur[3]);
                *(u32*)(hw + q*PB + 2*bb0)           = r1n0;
                *(u32*)(hw + q*PB + 2*bb0 + 16)      = r1n1;
                if (t + 2 < TLEN) {
                    size_t ri = (size_t)(t+2)*2048 + q*32 + bb0;
                    r1n0 = *(const u32*)(r1p + ri);
                    r1n1 = *(const u32*)(r1p + ri + 8);
                }
            } else {
                *(float2*)(scr + q*32 + bb0)     = make_float2(fmaxf(hcur[0],0.0f), fmaxf(hcur[1],0.0f));
                *(float2*)(scr + q*32 + bb0 + 8) = make_float2(fmaxf(hcur[2],0.0f), fmaxf(hcur[3],0.0f));
            }
            __syncthreads();
        }

        // ---- FC (collapsed) + window append ----
        if (tid < 32) {
            float s = *bcs + wcomb[64] * dsh[tid];
            #pragma unroll
            for (int uu = 0; uu < 64; uu++)
                s = fmaf(wcomb[uu], scr[uu*32 + tid], s);
            out[(size_t)(b0g + tid)*NSTEPS + step] = s;
            win[(TLEN + step)*32 + tid] = s;
        }
        __syncthreads();
    }
}

extern "C" void kernel_launch(void* const* d_in, const int* in_sizes, int n_in,
                              void* d_out, int out_size) {
    (void)in_sizes; (void)n_in; (void)out_size;
    const float* x    = (const float*)d_in[0];
    const float* Wih1 = (const float*)d_in[1];
    const float* Whh1 = (const float*)d_in[2];
    const float* bih1 = (const float*)d_in[3];
    const float* bhh1 = (const float*)d_in[4];
    const float* Wih2 = (const float*)d_in[5];
    const float* Whh2 = (const float*)d_in[6];
    const float* bih2 = (const float*)d_in[7];
    const float* bhh2 = (const float*)d_in[8];
    const float* fc1w = (const float*)d_in[9];
    const float* fc1b = (const float*)d_in[10];
    const float* fc2w = (const float*)d_in[11];
    const float* fc2b = (const float*)d_in[12];
    float* out = (float*)d_out;

    cudaFuncSetAttribute(lstm_rec_kernel, cudaFuncAttributeMaxDynamicSharedMemorySize, SMEM_BYTES);
    lstm_rec_kernel<<<GRID, NTHR, SMEM_BYTES>>>(x, Wih1, Whh1, bih1, bhh1,
                                                Wih2, Whh2, bih2, bhh2,
                                                fc1w, fc1b, fc2w, fc2b, out);
}